// round 12
// baseline (speedup 1.0000x reference)
#include <cuda_runtime.h>
#include <cuda_bf16.h>
#include <math.h>

// ---------------------------------------------------------------------------
// OutLook Attention, fp32 SIMT implementation.
// B=64, H=W=56, DIM=384, HEAD=12, HD=32, K=3, PAD=1, STRIDE=2, OUT_H=28, L=784
// ---------------------------------------------------------------------------

#define Bsz     64
#define Him     56
#define Wim     56
#define DIM     384
#define HEAD    12
#define HD      32
#define KK      3
#define OUTH    28
#define LWIN    (OUTH * OUTH)          // 784
#define HWpix   (Him * Wim)            // 3136
#define NLOG    (HEAD * KK * KK * KK * KK)  // 972
#define SCALE   0.17677669529663687f   // (DIM/HEAD)^-0.5 = 32^-0.5

#define M_BIG   (Bsz * HWpix)          // 200704
#define M_POOL  (Bsz * LWIN)           // 50176

// ----- scratch (device globals: allocation-free) ---------------------------
__device__ float g_V [(size_t)M_BIG  * DIM];   // value image   [B, HW, DIM]   308 MB
__device__ float g_XP[(size_t)M_POOL * DIM];   // pooled feats  [B, L,  DIM]    77 MB
__device__ float g_A [(size_t)M_POOL * NLOG];  // attn logits   [B, L,  972]   195 MB
__device__ float g_YF[(size_t)M_BIG  * DIM];   // folded output [B, HW, DIM]   308 MB

// ---------------------------------------------------------------------------
// Generic SGEMM: C[M,N] = A[M,K] * B[N,K]^T + bias[N]
// A row-major [M,K], B row-major [N,K], C row-major [M,N].
// Requirements: M % 128 == 0, K % 16 == 0, K row strides 16B-aligned.
// N edge handled by predication.
// ---------------------------------------------------------------------------
#define BM 128
#define BN 128
#define BK 16
#define TM 8
#define TN 8

__global__ __launch_bounds__(256)
void sgemm_bias_kernel(const float* __restrict__ A,
                       const float* __restrict__ B,
                       const float* __restrict__ bias,
                       float* __restrict__ C,
                       int M, int N, int K)
{
    __shared__ float As[BK][BM];
    __shared__ float Bs[BK][BN];

    const int tid = threadIdx.x;            // 0..255
    const int bm  = blockIdx.y * BM;
    const int bn  = blockIdx.x * BN;
    const int ty  = tid >> 4;                // 0..15
    const int tx  = tid & 15;                // 0..15

    float acc[TM][TN];
#pragma unroll
    for (int i = 0; i < TM; i++)
#pragma unroll
        for (int j = 0; j < TN; j++) acc[i][j] = 0.f;

    for (int k0 = 0; k0 < K; k0 += BK) {
        // ---- load A tile (128 rows x 16 k) as float4, store transposed ----
#pragma unroll
        for (int it = 0; it < 2; it++) {
            int f  = tid + it * 256;         // 0..511 float4 slots
            int r  = f >> 2;
            int c4 = (f & 3) << 2;
            float4 v = *reinterpret_cast<const float4*>(
                &A[(size_t)(bm + r) * K + k0 + c4]);
            As[c4 + 0][r] = v.x;
            As[c4 + 1][r] = v.y;
            As[c4 + 2][r] = v.z;
            As[c4 + 3][r] = v.w;
        }
        // ---- load B tile (128 n-rows x 16 k), guard n < N ----
#pragma unroll
        for (int it = 0; it < 2; it++) {
            int f  = tid + it * 256;
            int r  = f >> 2;
            int c4 = (f & 3) << 2;
            float4 v = make_float4(0.f, 0.f, 0.f, 0.f);
            if (bn + r < N)
                v = *reinterpret_cast<const float4*>(
                    &B[(size_t)(bn + r) * K + k0 + c4]);
            Bs[c4 + 0][r] = v.x;
            Bs[c4 + 1][r] = v.y;
            Bs[c4 + 2][r] = v.z;
            Bs[c4 + 3][r] = v.w;
        }
        __syncthreads();

#pragma unroll
        for (int kk = 0; kk < BK; kk++) {
            float a[TM], b[TN];
            const float4* a4 = reinterpret_cast<const float4*>(&As[kk][ty * TM]);
            const float4* b4 = reinterpret_cast<const float4*>(&Bs[kk][tx * TN]);
            float4 av0 = a4[0], av1 = a4[1];
            float4 bv0 = b4[0], bv1 = b4[1];
            a[0]=av0.x; a[1]=av0.y; a[2]=av0.z; a[3]=av0.w;
            a[4]=av1.x; a[5]=av1.y; a[6]=av1.z; a[7]=av1.w;
            b[0]=bv0.x; b[1]=bv0.y; b[2]=bv0.z; b[3]=bv0.w;
            b[4]=bv1.x; b[5]=bv1.y; b[6]=bv1.z; b[7]=bv1.w;
#pragma unroll
            for (int i = 0; i < TM; i++)
#pragma unroll
                for (int j = 0; j < TN; j++)
                    acc[i][j] = fmaf(a[i], b[j], acc[i][j]);
        }
        __syncthreads();
    }

    // ---- epilogue ----
#pragma unroll
    for (int i = 0; i < TM; i++) {
        int row = bm + ty * TM + i;
        size_t base = (size_t)row * N;
#pragma unroll
        for (int j = 0; j < TN; j++) {
            int col = bn + tx * TN + j;
            if (col < N) {
                float v = acc[i][j];
                if (bias) v += __ldg(&bias[col]);
                C[base + col] = v;
            }
        }
    }
}

// ---------------------------------------------------------------------------
// 2x2 average pool: x [B, HW, DIM] -> xp [B, L, DIM]
// ---------------------------------------------------------------------------
__global__ void pool_kernel(const float* __restrict__ x, float* __restrict__ xp)
{
    size_t idx = (size_t)blockIdx.x * blockDim.x + threadIdx.x;
    const size_t total = (size_t)M_POOL * DIM;
    if (idx >= total) return;
    int d = (int)(idx % DIM);
    size_t r = idx / DIM;
    int l = (int)(r % LWIN);
    int b = (int)(r / LWIN);
    int oh = l / OUTH, ow = l % OUTH;
    int h = oh * 2, w = ow * 2;
    const float* xb = x + (size_t)b * HWpix * DIM;
    float s = xb[((size_t)(h    ) * Wim + w    ) * DIM + d]
            + xb[((size_t)(h    ) * Wim + w + 1) * DIM + d]
            + xb[((size_t)(h + 1) * Wim + w    ) * DIM + d]
            + xb[((size_t)(h + 1) * Wim + w + 1) * DIM + d];
    xp[idx] = 0.25f * s;
}

// ---------------------------------------------------------------------------
// Softmax over groups of 9 (last axis of [B,L,HEAD,9,9]), scale applied first.
// g_A is updated in place. Groups = B*L*HEAD*9.
// ---------------------------------------------------------------------------
#define NGROUP ((size_t)M_POOL * HEAD * KK * KK)   // 5,419,008

__global__ void softmax9_kernel(float* __restrict__ a)
{
    size_t g = (size_t)blockIdx.x * blockDim.x + threadIdx.x;
    if (g >= NGROUP) return;
    size_t row = g / (HEAD * KK * KK);
    int    sub = (int)(g % (HEAD * KK * KK));
    float* p = a + row * NLOG + (size_t)sub * 9;

    float v[9];
    float m = -1e30f;
#pragma unroll
    for (int j = 0; j < 9; j++) { v[j] = p[j] * SCALE; m = fmaxf(m, v[j]); }
    float s = 0.f;
#pragma unroll
    for (int j = 0; j < 9; j++) { v[j] = expf(v[j] - m); s += v[j]; }
    float inv = 1.f / s;
#pragma unroll
    for (int j = 0; j < 9; j++) p[j] = v[j] * inv;
}

// ---------------------------------------------------------------------------
// Per-window attention apply + fold (scatter with atomics).
// One block per (b, l). 288 threads = (i in 0..8) x (d in 0..31).
// o[i, head*32+d] = sum_j A[head,i,j] * V[pix(j), head*32+d]
// scatter-add o[i,:] to folded image pixel pix(i) (skip padding).
// ---------------------------------------------------------------------------
__global__ __launch_bounds__(288)
void attn_apply_kernel(const float* __restrict__ Alog,
                       const float* __restrict__ V,
                       float* __restrict__ Yf)
{
    __shared__ float sA[NLOG];          // 972
    __shared__ float sV[9 * DIM];       // 3456

    const int bl = blockIdx.x;          // b*784 + l
    const int b  = bl / LWIN;
    const int l  = bl % LWIN;
    const int oh = l / OUTH, ow = l % OUTH;
    const int tid = threadIdx.x;

    const float* arow = Alog + (size_t)bl * NLOG;
    for (int t = tid; t < NLOG; t += 288) sA[t] = arow[t];

    const float* vb = V + (size_t)b * HWpix * DIM;
    for (int t = tid; t < 9 * DIM; t += 288) {
        int j = t / DIM, c = t % DIM;
        int di = j / KK, dj = j % KK;
        int h2 = oh * 2 - 1 + di;
        int w2 = ow * 2 - 1 + dj;
        float vv = 0.f;
        if (h2 >= 0 && h2 < Him && w2 >= 0 && w2 < Wim)
            vv = vb[((size_t)h2 * Wim + w2) * DIM + c];
        sV[t] = vv;
    }
    __syncthreads();

    const int i = tid >> 5;             // 0..8
    const int d = tid & 31;             // 0..31
    const int di = i / KK, dj = i % KK;
    const int h2 = oh * 2 - 1 + di;
    const int w2 = ow * 2 - 1 + dj;
    const bool ok = (h2 >= 0 && h2 < Him && w2 >= 0 && w2 < Wim);
    float* yrow = Yf + ((size_t)b * HWpix + (size_t)h2 * Wim + w2) * DIM;

#pragma unroll
    for (int head = 0; head < HEAD; head++) {
        const int c = head * HD + d;
        const float* ar = &sA[head * 81 + i * 9];
        float acc = 0.f;
#pragma unroll
        for (int j = 0; j < 9; j++)
            acc = fmaf(ar[j], sV[j * DIM + c], acc);
        if (ok) atomicAdd(&yrow[c], acc);
    }
}

// ---------------------------------------------------------------------------
// kernel_launch
// inputs: x[64,3136,384], Wv[384,384], Wa[972,384], ba[972], Wp[384,384], bp[384]
// output: y[64,3136,384] fp32
// ---------------------------------------------------------------------------
extern "C" void kernel_launch(void* const* d_in, const int* in_sizes, int n_in,
                              void* d_out, int out_size)
{
    const float* x  = (const float*)d_in[0];
    const float* Wv = (const float*)d_in[1];
    const float* Wa = (const float*)d_in[2];
    const float* ba = (const float*)d_in[3];
    const float* Wp = (const float*)d_in[4];
    const float* bp = (const float*)d_in[5];
    float* out = (float*)d_out;

    float *pV, *pXP, *pA, *pYF;
    cudaGetSymbolAddress((void**)&pV,  g_V);
    cudaGetSymbolAddress((void**)&pXP, g_XP);
    cudaGetSymbolAddress((void**)&pA,  g_A);
    cudaGetSymbolAddress((void**)&pYF, g_YF);

    // zero fold canvas (memset node, capturable)
    cudaMemsetAsync(pYF, 0, sizeof(float) * (size_t)M_BIG * DIM, 0);

    // GEMM1: V = x @ Wv^T           [200704,384] x [384,384]
    sgemm_bias_kernel<<<dim3(DIM / BN, M_BIG / BM), 256>>>(
        x, Wv, nullptr, pV, M_BIG, DIM, DIM);

    // pool: xp = avgpool2x2(x)
    {
        size_t total = (size_t)M_POOL * DIM;
        pool_kernel<<<(unsigned)((total + 255) / 256), 256>>>(x, pXP);
    }

    // GEMM2: logits = xp @ Wa^T + ba   [50176,384] x [384,972]
    sgemm_bias_kernel<<<dim3((NLOG + BN - 1) / BN, M_POOL / BM), 256>>>(
        pXP, Wa, ba, pA, M_POOL, NLOG, DIM);

    // softmax over last-9 groups (in place, scale applied)
    softmax9_kernel<<<(unsigned)((NGROUP + 255) / 256), 256>>>(pA);

    // per-window attention + fold (scatter)
    attn_apply_kernel<<<M_POOL, 288>>>(pA, pV, pYF);

    // GEMM3: out = Yf @ Wp^T + bp     [200704,384] x [384,384]
    sgemm_bias_kernel<<<dim3(DIM / BN, M_BIG / BM), 256>>>(
        pYF, Wp, bp, out, M_BIG, DIM, DIM);
}

// round 13
// speedup vs baseline: 1.7600x; 1.7600x over previous
#include <cuda_runtime.h>
#include <cuda_bf16.h>
#include <math.h>

// ---------------------------------------------------------------------------
// OutLook Attention. GEMMs via mma.sync tf32 (m16n8k8), rest fp32 SIMT.
// B=64, H=W=56, DIM=384, HEAD=12, HD=32, K=3, PAD=1, STRIDE=2, OUT_H=28, L=784
// ---------------------------------------------------------------------------

#define Bsz     64
#define Him     56
#define Wim     56
#define DIM     384
#define HEAD    12
#define HD      32
#define KK      3
#define OUTH    28
#define LWIN    (OUTH * OUTH)          // 784
#define HWpix   (Him * Wim)            // 3136
#define NLOG    (HEAD * KK * KK * KK * KK)  // 972
#define SCALE   0.17677669529663687f   // 32^-0.5

#define M_BIG   (Bsz * HWpix)          // 200704
#define M_POOL  (Bsz * LWIN)           // 50176

// ----- scratch (device globals: allocation-free) ---------------------------
__device__ float g_V [(size_t)M_BIG  * DIM];   // value image   [B, HW, DIM]
__device__ float g_XP[(size_t)M_POOL * DIM];   // pooled feats  [B, L,  DIM]
__device__ float g_A [(size_t)M_POOL * NLOG];  // attn logits   [B, L,  972]
__device__ float g_YF[(size_t)M_BIG  * DIM];   // folded output [B, HW, DIM]

// ---------------------------------------------------------------------------
// TF32 tensor-core GEMM: C[M,N] = A[M,K] * B[N,K]^T + bias[N]
// Block tile 128x128x32, 8 warps (2 M x 4 N), warp tile 64x32.
// mma.sync.aligned.m16n8k8.row.col.f32.tf32.tf32.f32
// Smem tiles stored in fragment order -> LDS.128 / LDS.64 fragment loads.
// Requires: M % 128 == 0, K % 32 == 0. N edge predicated.
// ---------------------------------------------------------------------------

__device__ __forceinline__ unsigned f2tf32(float f) {
    unsigned r;
    asm("cvt.rna.tf32.f32 %0, %1;" : "=r"(r) : "f"(f));
    return r;
}

__device__ __forceinline__ void mma_tf32(float c[4],
                                         const unsigned a[4],
                                         const unsigned b[2]) {
    asm volatile(
        "mma.sync.aligned.m16n8k8.row.col.f32.tf32.tf32.f32 "
        "{%0,%1,%2,%3}, {%4,%5,%6,%7}, {%8,%9}, {%0,%1,%2,%3};"
        : "+f"(c[0]), "+f"(c[1]), "+f"(c[2]), "+f"(c[3])
        : "r"(a[0]), "r"(a[1]), "r"(a[2]), "r"(a[3]),
          "r"(b[0]), "r"(b[1]));
}

#define GBM 128
#define GBN 128
#define GBK 32

__global__ __launch_bounds__(256, 1)
void gemm_tf32_kernel(const float* __restrict__ A,
                      const float* __restrict__ B,
                      const float* __restrict__ bias,
                      float* __restrict__ C,
                      int M, int N, int K)
{
    // fragment-order smem:
    // sA[((kstep*8 + mtile)*32 + lane)*4 + idx]   idx = (k>=4)*2 + (m>=8)
    // sB[((kstep*16 + ntile)*32 + lane)*2 + idx]  idx = (k>=4)
    __shared__ unsigned sA[4096];
    __shared__ unsigned sB[4096];

    const int tid  = threadIdx.x;
    const int lane = tid & 31;
    const int warp = tid >> 5;
    const int wm   = warp >> 2;          // 0..1  (M warp)
    const int wn   = warp & 3;           // 0..3  (N warp)
    const int g    = lane >> 2;          // groupID
    const int t    = lane & 3;           // thread-in-group
    const int bm   = blockIdx.y * GBM;
    const int bn   = blockIdx.x * GBN;

    float acc[4][4][4];
#pragma unroll
    for (int i = 0; i < 4; i++)
#pragma unroll
        for (int j = 0; j < 4; j++)
#pragma unroll
            for (int e = 0; e < 4; e++) acc[i][j][e] = 0.f;

    // staging registers (software pipeline across syncthreads)
    float4 va[4], vb[4];
    // per-thread staging coordinates: 4 float4 each for A and B tiles
    // f = tid + it*256, r = f>>3 (row), c4 = (f&7)*4 (k offset)
    int rA[4], cA[4];
#pragma unroll
    for (int it = 0; it < 4; it++) {
        int f = tid + it * 256;
        rA[it] = f >> 3;
        cA[it] = (f & 7) << 2;
    }

    const int KT = K / GBK;

    // ---- prologue: load first tiles into registers ----
#pragma unroll
    for (int it = 0; it < 4; it++) {
        va[it] = *reinterpret_cast<const float4*>(
            &A[(size_t)(bm + rA[it]) * K + cA[it]]);
        if (bn + rA[it] < N)
            vb[it] = *reinterpret_cast<const float4*>(
                &B[(size_t)(bn + rA[it]) * K + cA[it]]);
        else
            vb[it] = make_float4(0.f, 0.f, 0.f, 0.f);
    }

    for (int kt = 0; kt < KT; kt++) {
        // ---- stage regs -> smem (fragment order, tf32 convert) ----
#pragma unroll
        for (int it = 0; it < 4; it++) {
            int r = rA[it], c4 = cA[it];
            int kstep = c4 >> 3;
            int kh    = (c4 >> 2) & 1;
            // A element (m=r, k=c4+e)
            {
                int mtile = r >> 4;
                int gg    = r & 7;
                int rh    = (r >> 3) & 1;
                unsigned base = ((kstep * 8 + mtile) * 32 + gg * 4) * 4 + kh * 2 + rh;
                sA[base +  0] = f2tf32(va[it].x);
                sA[base +  4] = f2tf32(va[it].y);
                sA[base +  8] = f2tf32(va[it].z);
                sA[base + 12] = f2tf32(va[it].w);
            }
            // B element (n=r, k=c4+e)
            {
                int ntile = r >> 3;
                int gg    = r & 7;
                unsigned base = ((kstep * 16 + ntile) * 32 + gg * 4) * 2 + kh;
                sB[base + 0] = f2tf32(vb[it].x);
                sB[base + 2] = f2tf32(vb[it].y);
                sB[base + 4] = f2tf32(vb[it].z);
                sB[base + 6] = f2tf32(vb[it].w);
            }
        }
        __syncthreads();

        // ---- prefetch next gmem tile ----
        if (kt + 1 < KT) {
            int k0 = (kt + 1) * GBK;
#pragma unroll
            for (int it = 0; it < 4; it++) {
                va[it] = *reinterpret_cast<const float4*>(
                    &A[(size_t)(bm + rA[it]) * K + k0 + cA[it]]);
                if (bn + rA[it] < N)
                    vb[it] = *reinterpret_cast<const float4*>(
                        &B[(size_t)(bn + rA[it]) * K + k0 + cA[it]]);
                else
                    vb[it] = make_float4(0.f, 0.f, 0.f, 0.f);
            }
        }

        // ---- compute: 4 k-steps of m16n8k8 ----
#pragma unroll
        for (int s = 0; s < 4; s++) {
            unsigned af[4][4];
            unsigned bf[4][2];
#pragma unroll
            for (int mt = 0; mt < 4; mt++) {
                const uint4 v = *reinterpret_cast<const uint4*>(
                    &sA[((s * 8 + wm * 4 + mt) * 32 + lane) * 4]);
                af[mt][0] = v.x; af[mt][1] = v.y; af[mt][2] = v.z; af[mt][3] = v.w;
            }
#pragma unroll
            for (int nt = 0; nt < 4; nt++) {
                const uint2 v = *reinterpret_cast<const uint2*>(
                    &sB[((s * 16 + wn * 4 + nt) * 32 + lane) * 2]);
                bf[nt][0] = v.x; bf[nt][1] = v.y;
            }
#pragma unroll
            for (int mt = 0; mt < 4; mt++)
#pragma unroll
                for (int nt = 0; nt < 4; nt++)
                    mma_tf32(acc[mt][nt], af[mt], bf[nt]);
        }
        __syncthreads();
    }

    // ---- epilogue ----
#pragma unroll
    for (int mt = 0; mt < 4; mt++) {
        int row0 = bm + wm * 64 + mt * 16 + g;
#pragma unroll
        for (int nt = 0; nt < 4; nt++) {
            int col = bn + wn * 32 + nt * 8 + 2 * t;
            if (col < N) {
                float bx = 0.f, by = 0.f;
                if (bias) { bx = __ldg(&bias[col]); by = __ldg(&bias[col + 1]); }
                float2 v0 = make_float2(acc[mt][nt][0] + bx, acc[mt][nt][1] + by);
                float2 v1 = make_float2(acc[mt][nt][2] + bx, acc[mt][nt][3] + by);
                *reinterpret_cast<float2*>(&C[(size_t)row0 * N + col])       = v0;
                *reinterpret_cast<float2*>(&C[(size_t)(row0 + 8) * N + col]) = v1;
            }
        }
    }
}

// ---------------------------------------------------------------------------
// 2x2 average pool: x [B, HW, DIM] -> xp [B, L, DIM]
// ---------------------------------------------------------------------------
__global__ void pool_kernel(const float* __restrict__ x, float* __restrict__ xp)
{
    size_t idx = (size_t)blockIdx.x * blockDim.x + threadIdx.x;
    const size_t total = (size_t)M_POOL * DIM;
    if (idx >= total) return;
    int d = (int)(idx % DIM);
    size_t r = idx / DIM;
    int l = (int)(r % LWIN);
    int b = (int)(r / LWIN);
    int oh = l / OUTH, ow = l % OUTH;
    int h = oh * 2, w = ow * 2;
    const float* xb = x + (size_t)b * HWpix * DIM;
    float s = xb[((size_t)(h    ) * Wim + w    ) * DIM + d]
            + xb[((size_t)(h    ) * Wim + w + 1) * DIM + d]
            + xb[((size_t)(h + 1) * Wim + w    ) * DIM + d]
            + xb[((size_t)(h + 1) * Wim + w + 1) * DIM + d];
    xp[idx] = 0.25f * s;
}

// ---------------------------------------------------------------------------
// Softmax over groups of 9 (last axis of [B,L,HEAD,9,9]), scale applied.
// ---------------------------------------------------------------------------
#define NGROUP ((size_t)M_POOL * HEAD * KK * KK)   // 5,419,008

__global__ void softmax9_kernel(float* __restrict__ a)
{
    size_t gg = (size_t)blockIdx.x * blockDim.x + threadIdx.x;
    if (gg >= NGROUP) return;
    size_t row = gg / (HEAD * KK * KK);
    int    sub = (int)(gg % (HEAD * KK * KK));
    float* p = a + row * NLOG + (size_t)sub * 9;

    float v[9];
    float m = -1e30f;
#pragma unroll
    for (int j = 0; j < 9; j++) { v[j] = p[j] * SCALE; m = fmaxf(m, v[j]); }
    float s = 0.f;
#pragma unroll
    for (int j = 0; j < 9; j++) { v[j] = expf(v[j] - m); s += v[j]; }
    float inv = 1.f / s;
#pragma unroll
    for (int j = 0; j < 9; j++) p[j] = v[j] * inv;
}

// ---------------------------------------------------------------------------
// Per-window attention apply + fold (scatter with atomics).
// ---------------------------------------------------------------------------
__global__ __launch_bounds__(288)
void attn_apply_kernel(const float* __restrict__ Alog,
                       const float* __restrict__ V,
                       float* __restrict__ Yf)
{
    __shared__ float sAt[NLOG];         // 972
    __shared__ float sV[9 * DIM];       // 3456

    const int bl = blockIdx.x;          // b*784 + l
    const int b  = bl / LWIN;
    const int l  = bl % LWIN;
    const int oh = l / OUTH, ow = l % OUTH;
    const int tid = threadIdx.x;

    const float* arow = Alog + (size_t)bl * NLOG;
    for (int tt = tid; tt < NLOG; tt += 288) sAt[tt] = arow[tt];

    const float* vb = V + (size_t)b * HWpix * DIM;
    for (int tt = tid; tt < 9 * DIM; tt += 288) {
        int j = tt / DIM, c = tt % DIM;
        int di = j / KK, dj = j % KK;
        int h2 = oh * 2 - 1 + di;
        int w2 = ow * 2 - 1 + dj;
        float vv = 0.f;
        if (h2 >= 0 && h2 < Him && w2 >= 0 && w2 < Wim)
            vv = vb[((size_t)h2 * Wim + w2) * DIM + c];
        sV[tt] = vv;
    }
    __syncthreads();

    const int i = tid >> 5;             // 0..8
    const int d = tid & 31;             // 0..31
    const int di = i / KK, dj = i % KK;
    const int h2 = oh * 2 - 1 + di;
    const int w2 = ow * 2 - 1 + dj;
    const bool ok = (h2 >= 0 && h2 < Him && w2 >= 0 && w2 < Wim);
    float* yrow = Yf + ((size_t)b * HWpix + (size_t)h2 * Wim + w2) * DIM;

#pragma unroll
    for (int head = 0; head < HEAD; head++) {
        const int c = head * HD + d;
        const float* ar = &sAt[head * 81 + i * 9];
        float acc = 0.f;
#pragma unroll
        for (int j = 0; j < 9; j++)
            acc = fmaf(ar[j], sV[j * DIM + c], acc);
        if (ok) atomicAdd(&yrow[c], acc);
    }
}

// ---------------------------------------------------------------------------
// kernel_launch
// inputs: x[64,3136,384], Wv[384,384], Wa[972,384], ba[972], Wp[384,384], bp[384]
// output: y[64,3136,384] fp32
// ---------------------------------------------------------------------------
extern "C" void kernel_launch(void* const* d_in, const int* in_sizes, int n_in,
                              void* d_out, int out_size)
{
    const float* x  = (const float*)d_in[0];
    const float* Wv = (const float*)d_in[1];
    const float* Wa = (const float*)d_in[2];
    const float* ba = (const float*)d_in[3];
    const float* Wp = (const float*)d_in[4];
    const float* bp = (const float*)d_in[5];
    float* out = (float*)d_out;

    float *pV, *pXP, *pA, *pYF;
    cudaGetSymbolAddress((void**)&pV,  g_V);
    cudaGetSymbolAddress((void**)&pXP, g_XP);
    cudaGetSymbolAddress((void**)&pA,  g_A);
    cudaGetSymbolAddress((void**)&pYF, g_YF);

    // zero fold canvas (memset node, capturable)
    cudaMemsetAsync(pYF, 0, sizeof(float) * (size_t)M_BIG * DIM, 0);

    // GEMM1: V = x @ Wv^T           [200704,384] x [384,384]
    gemm_tf32_kernel<<<dim3(DIM / GBN, M_BIG / GBM), 256>>>(
        x, Wv, nullptr, pV, M_BIG, DIM, DIM);

    // pool: xp = avgpool2x2(x)
    {
        size_t total = (size_t)M_POOL * DIM;
        pool_kernel<<<(unsigned)((total + 255) / 256), 256>>>(x, pXP);
    }

    // GEMM2: logits = xp @ Wa^T + ba   [50176,384] x [384,972]
    gemm_tf32_kernel<<<dim3((NLOG + GBN - 1) / GBN, M_POOL / GBM), 256>>>(
        pXP, Wa, ba, pA, M_POOL, NLOG, DIM);

    // softmax over last-9 groups (in place, scale applied)
    softmax9_kernel<<<(unsigned)((NGROUP + 255) / 256), 256>>>(pA);

    // per-window attention + fold (scatter)
    attn_apply_kernel<<<M_POOL, 288>>>(pA, pV, pYF);

    // GEMM3: out = Yf @ Wp^T + bp     [200704,384] x [384,384]
    gemm_tf32_kernel<<<dim3(DIM / GBN, M_BIG / GBM), 256>>>(
        pYF, Wp, bp, out, M_BIG, DIM, DIM);
}